// round 1
// baseline (speedup 1.0000x reference)
#include <cuda_runtime.h>

#define NB_VARS 2000000
#define M0 4000000
#define M1 1000000
#define M2 500000
#define M3 125000
#define E1 8000000
#define E3 1000000

// Scratch (allocation-free rule: __device__ globals)
__device__ float g_y0[M0];
__device__ float g_y1[M1];
__device__ float g_y2[M2];

// Fused input encoding: x = [0, 1, p0, 1-p0, p1, 1-p1, ...]
__device__ __forceinline__ float leaf_val(const float* __restrict__ xp, int idx) {
    if (idx >= 2) {
        float p = __ldg(xp + ((idx - 2) >> 1));
        return (idx & 1) ? (1.0f - p) : p;
    }
    return (float)idx;  // idx 0 -> 0.0, idx 1 -> 1.0
}

__global__ void zero_kernel(float* __restrict__ out) {
    int i = blockIdx.x * blockDim.x + threadIdx.x;
    if (i < M1) g_y1[i] = 0.0f;
    if (i < M3) out[i] = 0.0f;
}

// Layer 0: binary product layer. Each thread handles 2 products via one int4 load.
__global__ void layer0_kernel(const float* __restrict__ xp, const int4* __restrict__ ix) {
    int t = blockIdx.x * blockDim.x + threadIdx.x;
    if (t >= M0 / 2) return;
    int4 v = __ldg(ix + t);
    float a = leaf_val(xp, v.x) * leaf_val(xp, v.y);
    float b = leaf_val(xp, v.z) * leaf_val(xp, v.w);
    g_y0[2 * t + 0] = a;
    g_y0[2 * t + 1] = b;
}

// Layer 2: binary product layer over g_y1 -> g_y2.
__global__ void layer2_kernel(const int4* __restrict__ ix) {
    int t = blockIdx.x * blockDim.x + threadIdx.x;
    if (t >= M2 / 2) return;
    int4 v = __ldg(ix + t);
    float a = g_y1[v.x] * g_y1[v.y];
    float b = g_y1[v.z] * g_y1[v.w];
    g_y2[2 * t + 0] = a;
    g_y2[2 * t + 1] = b;
}

// Sorted segment-sum: gather + warp segmented inclusive scan + one atomic per run tail.
__device__ __forceinline__ void segsum_body(const int* __restrict__ ix_in,
                                            const int* __restrict__ ix_out,
                                            const float* __restrict__ src,
                                            float* __restrict__ dst, int n) {
    int e = blockIdx.x * blockDim.x + threadIdx.x;
    const unsigned full = 0xFFFFFFFFu;
    int lane = threadIdx.x & 31;
    int seg = -1;
    float v = 0.0f;
    if (e < n) {
        seg = __ldg(ix_out + e);
        v = __ldg(src + __ldg(ix_in + e));
    }
    // Segmented inclusive scan within warp
    #pragma unroll
    for (int d = 1; d < 32; d <<= 1) {
        float ov = __shfl_up_sync(full, v, d);
        int   os = __shfl_up_sync(full, seg, d);
        if (lane >= d && os == seg) v += ov;
    }
    int nseg = __shfl_down_sync(full, seg, 1);
    if (seg >= 0 && (lane == 31 || nseg != seg)) {
        atomicAdd(dst + seg, v);
    }
}

__global__ void segsum1_kernel(const int* __restrict__ ix_in,
                               const int* __restrict__ ix_out) {
    segsum_body(ix_in, ix_out, g_y0, g_y1, E1);
}

__global__ void segsum3_kernel(const int* __restrict__ ix_in,
                               const int* __restrict__ ix_out,
                               float* __restrict__ out) {
    segsum_body(ix_in, ix_out, g_y2, out, E3);
}

extern "C" void kernel_launch(void* const* d_in, const int* in_sizes, int n_in,
                              void* d_out, int out_size) {
    const float* x_pos  = (const float*)d_in[0];
    const int*   ix_in0 = (const int*)d_in[1];
    const int*   ix_in1 = (const int*)d_in[2];
    const int*   ix_out1= (const int*)d_in[3];
    const int*   ix_in2 = (const int*)d_in[4];
    const int*   ix_in3 = (const int*)d_in[5];
    const int*   ix_out3= (const int*)d_in[6];
    float* out = (float*)d_out;

    const int B = 256;
    zero_kernel  <<<(M1 + B - 1) / B, B>>>(out);
    layer0_kernel<<<(M0 / 2 + B - 1) / B, B>>>(x_pos, (const int4*)ix_in0);
    segsum1_kernel<<<(E1 + B - 1) / B, B>>>(ix_in1, ix_out1);
    layer2_kernel<<<(M2 / 2 + B - 1) / B, B>>>((const int4*)ix_in2);
    segsum3_kernel<<<(E3 + B - 1) / B, B>>>(ix_in3, ix_out3, out);
}

// round 2
// speedup vs baseline: 1.1719x; 1.1719x over previous
#include <cuda_runtime.h>

#define NB_VARS 2000000
#define M0 4000000
#define M1 1000000
#define M2 500000
#define M3 125000
#define E1 8000000
#define E3 1000000

// Scratch (allocation-free rule: __device__ globals)
__device__ float g_y0[M0];
__device__ float g_y1[M1];
__device__ float g_y2[M2];

// Fused input encoding: x = [0, 1, p0, 1-p0, p1, 1-p1, ...]
__device__ __forceinline__ float leaf_val(const float* __restrict__ xp, int idx) {
    if (idx >= 2) {
        float p = __ldg(xp + ((idx - 2) >> 1));
        return (idx & 1) ? (1.0f - p) : p;
    }
    return (float)idx;  // 0 -> 0.0, 1 -> 1.0
}

// Layer 0: 4 products per thread (8 gathers in flight), float4 store.
// Also zeroes g_y1 and d_out (must happen before the segsum kernels; stream order guarantees it).
__global__ void __launch_bounds__(256) layer0_kernel(const float* __restrict__ xp,
                                                     const int4* __restrict__ ix,
                                                     float* __restrict__ out_zero) {
    int t = blockIdx.x * blockDim.x + threadIdx.x;     // [0, M0/4)
    if (t < M1 / 4) ((float4*)g_y1)[t] = make_float4(0.f, 0.f, 0.f, 0.f);
    if (t < M3 / 4) ((float4*)out_zero)[t] = make_float4(0.f, 0.f, 0.f, 0.f);
    if (t >= M0 / 4) return;
    int4 a = __ldg(ix + 2 * t);
    int4 b = __ldg(ix + 2 * t + 1);
    float4 r;
    r.x = leaf_val(xp, a.x) * leaf_val(xp, a.y);
    r.y = leaf_val(xp, a.z) * leaf_val(xp, a.w);
    r.z = leaf_val(xp, b.x) * leaf_val(xp, b.y);
    r.w = leaf_val(xp, b.z) * leaf_val(xp, b.w);
    ((float4*)g_y0)[t] = r;
}

// Layer 2: 4 products per thread over g_y1 -> g_y2.
__global__ void __launch_bounds__(256) layer2_kernel(const int4* __restrict__ ix) {
    int t = blockIdx.x * blockDim.x + threadIdx.x;     // [0, M2/4)
    if (t >= M2 / 4) return;
    int4 a = __ldg(ix + 2 * t);
    int4 b = __ldg(ix + 2 * t + 1);
    float4 r;
    r.x = g_y1[a.x] * g_y1[a.y];
    r.y = g_y1[a.z] * g_y1[a.w];
    r.z = g_y1[b.x] * g_y1[b.y];
    r.w = g_y1[b.z] * g_y1[b.w];
    ((float4*)g_y2)[t] = r;
}

// Sorted segment-sum, 4 edges/thread:
//  - local run-merge (interior runs -> direct atomicAdd, statistically rare)
//  - ballot-based warp segmented scan over per-thread tail runs
//  - one atomicAdd per run end
__device__ __forceinline__ void segsum4(const int4* __restrict__ ix_in,
                                        const int4* __restrict__ ix_out,
                                        const float* __restrict__ src,
                                        float* __restrict__ dst, int nthreads) {
    const unsigned full = 0xFFFFFFFFu;
    int t = blockIdx.x * blockDim.x + threadIdx.x;
    int lane = threadIdx.x & 31;

    int4 s;
    float v0 = 0.f, v1 = 0.f, v2 = 0.f, v3 = 0.f;
    if (t < nthreads) {
        s = __ldg(ix_out + t);
        int4 g = __ldg(ix_in + t);
        v0 = __ldg(src + g.x);
        v1 = __ldg(src + g.y);
        v2 = __ldg(src + g.z);
        v3 = __ldg(src + g.w);
    } else {
        s = make_int4(-1, -1, -1, -1);   // sentinel: inert in scan, never flushed
    }

    bool e01 = (s.x == s.y), e12 = (s.y == s.z), e23 = (s.z == s.w);

    // Interior complete runs (not touching edge 0 or 3): flush directly.
    if (!e01 && e12 && !e23) {
        atomicAdd(dst + s.y, v1 + v2);
    } else {
        if (!e01 && !e12) atomicAdd(dst + s.y, v1);
        if (!e12 && !e23) atomicAdd(dst + s.z, v2);
    }

    // Head run value (edges with seg==s.x) and tail run value (seg==s.w).
    float vh = v0 + (e01 ? (v1 + (e12 ? (v2 + (e23 ? v3 : 0.f)) : 0.f)) : 0.f);
    float vt = v3 + (e23 ? (v2 + (e12 ? (v1 + (e01 ? v0 : 0.f)) : 0.f)) : 0.f);
    bool open = (s.x == s.w);            // whole thread is one run (vh==vt==total)

    // Chain: c = accumulated value of the run containing this thread's tail.
    int prevTail = __shfl_up_sync(full, s.w, 1);
    bool head = (lane == 0) || !(open && prevTail == s.x);
    unsigned hb = __ballot_sync(full, head);
    unsigned mask_le = 0xFFFFFFFFu >> (31 - lane);
    int segstart = 31 - __clz(hb & mask_le);

    float c = vt;
    #pragma unroll
    for (int d = 1; d < 32; d <<= 1) {
        float o = __shfl_up_sync(full, c, d);
        if (lane - d >= segstart) c += o;
    }
    float cprev = __shfl_up_sync(full, c, 1);

    // Closed thread: its head run ends here -> flush (absorbing prev chain if connected).
    if (!open && s.x >= 0) {
        float h = vh + ((lane > 0 && prevTail == s.x) ? cprev : 0.f);
        atomicAdd(dst + s.x, h);
    }
    // Tail run ends here if the next lane doesn't continue it.
    int s0next = __shfl_down_sync(full, s.x, 1);
    if (s.w >= 0 && (lane == 31 || s0next != s.w)) {
        atomicAdd(dst + s.w, c);
    }
}

__global__ void __launch_bounds__(256) segsum1_kernel(const int4* __restrict__ ix_in,
                                                      const int4* __restrict__ ix_out) {
    segsum4(ix_in, ix_out, g_y0, g_y1, E1 / 4);
}

__global__ void __launch_bounds__(256) segsum3_kernel(const int4* __restrict__ ix_in,
                                                      const int4* __restrict__ ix_out,
                                                      float* __restrict__ out) {
    segsum4(ix_in, ix_out, g_y2, out, E3 / 4);
}

extern "C" void kernel_launch(void* const* d_in, const int* in_sizes, int n_in,
                              void* d_out, int out_size) {
    const float* x_pos   = (const float*)d_in[0];
    const int*   ix_in0  = (const int*)d_in[1];
    const int*   ix_in1  = (const int*)d_in[2];
    const int*   ix_out1 = (const int*)d_in[3];
    const int*   ix_in2  = (const int*)d_in[4];
    const int*   ix_in3  = (const int*)d_in[5];
    const int*   ix_out3 = (const int*)d_in[6];
    float* out = (float*)d_out;

    const int B = 256;
    layer0_kernel <<<(M0 / 4 + B - 1) / B, B>>>(x_pos, (const int4*)ix_in0, out);
    segsum1_kernel<<<(E1 / 4 + B - 1) / B, B>>>((const int4*)ix_in1, (const int4*)ix_out1);
    layer2_kernel <<<(M2 / 4 + B - 1) / B, B>>>((const int4*)ix_in2);
    segsum3_kernel<<<(E3 / 4 + B - 1) / B, B>>>((const int4*)ix_in3, (const int4*)ix_out3, out);
}